// round 1
// baseline (speedup 1.0000x reference)
#include <cuda_runtime.h>
#include <cstdint>

// ---------------------------------------------------------------------------
// MLPGraphNetwork: edge MLP -> segment_sum -> node MLP -> global MLP
// Fully fused fp32 implementation using packed fma.rn.f32x2 (FFMA2).
// ---------------------------------------------------------------------------

#define TPB 256

#define TILE_E 128
#define RPW_E  16     // rows per warp (edge kernel)
#define SA_E   132    // smem activation stride (edge)

#define TILE_N 64
#define RPW_N  8
#define SA_N   164    // node layer-1 input stride (160 wide)
#define SB_N   132    // node hidden stride

#define MAX_NODES 50000

// Scratch (static device globals are the allowed scratch mechanism)
__device__ float g_agg[MAX_NODES * 128];
__device__ float g_esum[128];
__device__ float g_nsum[128];
__device__ int   g_is64;

// ---------------- packed f32x2 helpers ----------------
__device__ __forceinline__ unsigned long long pk2(float a, float b) {
    unsigned long long r;
    asm("mov.b64 %0, {%1,%2};" : "=l"(r) : "f"(a), "f"(b));
    return r;
}
__device__ __forceinline__ float2 upk2(unsigned long long v) {
    float2 r;
    asm("mov.b64 {%0,%1}, %2;" : "=f"(r.x), "=f"(r.y) : "l"(v));
    return r;
}
__device__ __forceinline__ void fma2(unsigned long long& d,
                                     unsigned long long a,
                                     unsigned long long b) {
    asm("fma.rn.f32x2 %0, %1, %2, %0;" : "+l"(d) : "l"(a), "l"(b));
}

// ---------------- shared-memory GEMM tile ----------------
// Block = 256 threads = 8 warps. Each warp computes RPW rows x 128 cols.
// Lane owns 4 consecutive output columns (c0 = lane*4), accumulated as two
// f32x2 pairs per row. Weights in smem row-major [KIN][128]. Bias preloaded.
template <int KIN, int RPW, int STRIDE>
__device__ __forceinline__ void gemm_tile(const float* __restrict__ sIn,
                                          const float* __restrict__ sW,
                                          const float* __restrict__ gB,
                                          unsigned long long acc[RPW][2]) {
    const int lane = threadIdx.x & 31;
    const int warp = threadIdx.x >> 5;
    const int c0 = lane << 2;
    const float4 b = *(const float4*)(gB + c0);
    const unsigned long long b0 = pk2(b.x, b.y), b1 = pk2(b.z, b.w);
#pragma unroll
    for (int r = 0; r < RPW; r++) { acc[r][0] = b0; acc[r][1] = b1; }

    const float* inBase = sIn + warp * RPW * STRIDE;
#pragma unroll 1
    for (int kk = 0; kk < KIN; kk += 4) {
        const float4 w0 = *(const float4*)(sW + (kk + 0) * 128 + c0);
        const float4 w1 = *(const float4*)(sW + (kk + 1) * 128 + c0);
        const float4 w2 = *(const float4*)(sW + (kk + 2) * 128 + c0);
        const float4 w3 = *(const float4*)(sW + (kk + 3) * 128 + c0);
        unsigned long long wd[4][2];
        wd[0][0] = pk2(w0.x, w0.y); wd[0][1] = pk2(w0.z, w0.w);
        wd[1][0] = pk2(w1.x, w1.y); wd[1][1] = pk2(w1.z, w1.w);
        wd[2][0] = pk2(w2.x, w2.y); wd[2][1] = pk2(w2.z, w2.w);
        wd[3][0] = pk2(w3.x, w3.y); wd[3][1] = pk2(w3.z, w3.w);
#pragma unroll
        for (int r = 0; r < RPW; r++) {
            const float4 a = *(const float4*)(inBase + r * STRIDE + kk);
            unsigned long long t;
            t = pk2(a.x, a.x); fma2(acc[r][0], t, wd[0][0]); fma2(acc[r][1], t, wd[0][1]);
            t = pk2(a.y, a.y); fma2(acc[r][0], t, wd[1][0]); fma2(acc[r][1], t, wd[1][1]);
            t = pk2(a.z, a.z); fma2(acc[r][0], t, wd[2][0]); fma2(acc[r][1], t, wd[2][1]);
            t = pk2(a.w, a.w); fma2(acc[r][0], t, wd[3][0]); fma2(acc[r][1], t, wd[3][1]);
        }
    }
}

template <int RPW, int STRIDE, bool RELU>
__device__ __forceinline__ void store_act(unsigned long long acc[RPW][2],
                                          float* __restrict__ sOut) {
    const int lane = threadIdx.x & 31;
    const int warp = threadIdx.x >> 5;
    const int c0 = lane << 2;
#pragma unroll
    for (int r = 0; r < RPW; r++) {
        float2 lo = upk2(acc[r][0]);
        float2 hi = upk2(acc[r][1]);
        float4 v = make_float4(lo.x, lo.y, hi.x, hi.y);
        if (RELU) {
            v.x = fmaxf(v.x, 0.f); v.y = fmaxf(v.y, 0.f);
            v.z = fmaxf(v.z, 0.f); v.w = fmaxf(v.w, 0.f);
        }
        *(float4*)(sOut + (warp * RPW + r) * STRIDE + c0) = v;
    }
}

__device__ __forceinline__ void stage_w(float* __restrict__ sW,
                                        const float* __restrict__ gW, int n4) {
    const float4* s = (const float4*)gW;
    float4* d = (float4*)sW;
    for (int i = threadIdx.x; i < n4; i += TPB) d[i] = s[i];
}

// ---------------- dtype detection for edge_index ----------------
// If indices are int64 (little-endian, values < 2^31), every odd 32-bit word
// is zero. With int32 data those words are random node ids, virtually never
// all zero across 2048 samples.
__global__ void detect_kernel(const unsigned* __restrict__ p, int E) {
    if (threadIdx.x == 0) g_is64 = 1;
    __syncthreads();
    const int n = E < 2048 ? E : 2048;
    bool nz = false;
    for (int i = threadIdx.x; i < n; i += TPB)
        if (p[2 * i + 1] != 0) nz = true;
    if (nz) g_is64 = 0;
}

__global__ void zero_kernel(long long total) {
    long long i = (long long)blockIdx.x * blockDim.x + threadIdx.x;
    const long long stride = (long long)gridDim.x * blockDim.x;
    for (; i < total; i += stride) g_agg[i] = 0.f;
    if (blockIdx.x == 0 && threadIdx.x < 128) {
        g_esum[threadIdx.x] = 0.f;
        g_nsum[threadIdx.x] = 0.f;
    }
}

// ---------------- edge kernel: fused 4-layer MLP + segment_sum ----------------
__global__ void __launch_bounds__(TPB)
edge_kernel(const float* __restrict__ x, const float* __restrict__ ea,
            const float* __restrict__ u, const void* __restrict__ ei,
            const float* __restrict__ w1, const float* __restrict__ b1,
            const float* __restrict__ w2, const float* __restrict__ b2,
            const float* __restrict__ w3, const float* __restrict__ b3,
            const float* __restrict__ w4, const float* __restrict__ b4,
            float* __restrict__ e_out, int N, int E) {
    extern __shared__ float sm[];
    float* bufA = sm;                          // TILE_E * SA_E
    float* bufB = bufA + TILE_E * SA_E;        // TILE_E * SA_E
    float* sW   = bufB + TILE_E * SA_E;        // 128 * 128
    int* sSrc = (int*)(sW + 128 * 128);
    int* sDst = sSrc + TILE_E;

    const int tid = threadIdx.x;
    const long long eBase = (long long)blockIdx.x * TILE_E;
    const int is64 = g_is64;

    for (int i = tid; i < TILE_E; i += TPB) {
        long long e = eBase + i;
        int s = 0, d = 0;
        if (e < E) {
            if (is64) {
                const long long* q = (const long long*)ei;
                s = (int)q[e]; d = (int)q[E + e];
            } else {
                const int* q = (const int*)ei;
                s = q[e]; d = q[E + e];
            }
        }
        sSrc[i] = s; sDst[i] = d;
    }
    __syncthreads();

    // Stage concat([edge_attr, x[src], x[dst], u]) into bufA (64 wide)
    const float4* x4 = (const float4*)x;
    const float4* ea4 = (const float4*)ea;
    const float4* u4 = (const float4*)u;
    for (int i = tid; i < TILE_E * 4; i += TPB) {
        const int r = i >> 2, q = i & 3;
        const long long e = eBase + r;
        float4 z = make_float4(0.f, 0.f, 0.f, 0.f);
        float4 va = z, vs = z, vd = z, vu = z;
        if (e < E) {
            va = ea4[e * 4 + q];
            vs = x4[(long long)sSrc[r] * 4 + q];
            vd = x4[(long long)sDst[r] * 4 + q];
            vu = u4[q];
        }
        float* row = bufA + r * SA_E;
        *(float4*)(row + q * 4)      = va;
        *(float4*)(row + 16 + q * 4) = vs;
        *(float4*)(row + 32 + q * 4) = vd;
        *(float4*)(row + 48 + q * 4) = vu;
    }
    stage_w(sW, w1, 64 * 128 / 4);
    __syncthreads();

    unsigned long long acc[RPW_E][2];
    gemm_tile<64, RPW_E, SA_E>(bufA, sW, b1, acc);
    store_act<RPW_E, SA_E, true>(acc, bufB);
    __syncthreads();
    stage_w(sW, w2, 128 * 128 / 4);
    __syncthreads();
    gemm_tile<128, RPW_E, SA_E>(bufB, sW, b2, acc);
    store_act<RPW_E, SA_E, true>(acc, bufA);
    __syncthreads();
    stage_w(sW, w3, 128 * 128 / 4);
    __syncthreads();
    gemm_tile<128, RPW_E, SA_E>(bufA, sW, b3, acc);
    store_act<RPW_E, SA_E, true>(acc, bufB);
    __syncthreads();
    stage_w(sW, w4, 128 * 128 / 4);
    __syncthreads();
    gemm_tile<128, RPW_E, SA_E>(bufB, sW, b4, acc);

    // Epilogue: write e_out, atomic segment-sum into g_agg, column sums
    const int lane = tid & 31, warp = tid >> 5, c0 = lane << 2;
    float cs0 = 0.f, cs1 = 0.f, cs2 = 0.f, cs3 = 0.f;
#pragma unroll
    for (int r = 0; r < RPW_E; r++) {
        const int row = warp * RPW_E + r;
        const long long e = eBase + row;
        if (e < E) {
            float2 lo = upk2(acc[r][0]);
            float2 hi = upk2(acc[r][1]);
            float4 v = make_float4(lo.x, lo.y, hi.x, hi.y);
            *(float4*)(e_out + e * 128 + c0) = v;
            float* ap = g_agg + (long long)sDst[row] * 128 + c0;
            atomicAdd(ap + 0, v.x); atomicAdd(ap + 1, v.y);
            atomicAdd(ap + 2, v.z); atomicAdd(ap + 3, v.w);
            cs0 += v.x; cs1 += v.y; cs2 += v.z; cs3 += v.w;
        }
    }
    __syncthreads();
    *(float4*)(bufA + warp * 128 + c0) = make_float4(cs0, cs1, cs2, cs3);
    __syncthreads();
    if (tid < 128) {
        float s = 0.f;
#pragma unroll
        for (int w = 0; w < 8; w++) s += bufA[w * 128 + tid];
        atomicAdd(&g_esum[tid], s);
    }
}

// ---------------- node kernel: fused 4-layer MLP ----------------
__global__ void __launch_bounds__(TPB)
node_kernel(const float* __restrict__ x, const float* __restrict__ u,
            const float* __restrict__ w1, const float* __restrict__ b1,
            const float* __restrict__ w2, const float* __restrict__ b2,
            const float* __restrict__ w3, const float* __restrict__ b3,
            const float* __restrict__ w4, const float* __restrict__ b4,
            float* __restrict__ n_out, int N) {
    extern __shared__ float sm[];
    float* bufA = sm;                       // TILE_N * SA_N
    float* bufB = bufA + TILE_N * SA_N;     // TILE_N * SB_N
    float* sW   = bufB + TILE_N * SB_N;     // 160 * 128

    const int tid = threadIdx.x;
    const long long nBase = (long long)blockIdx.x * TILE_N;
    const float4* x4 = (const float4*)x;
    const float4* u4 = (const float4*)u;
    const float4* agg4 = (const float4*)g_agg;

    // Stage concat([x, agg, u]) (160 wide)
    for (int i = tid; i < TILE_N * 32; i += TPB) {
        const int r = i >> 5, q = i & 31;
        const long long n = nBase + r;
        float4 v = (n < N) ? agg4[n * 32 + q] : make_float4(0.f, 0.f, 0.f, 0.f);
        *(float4*)(bufA + r * SA_N + 16 + q * 4) = v;
    }
    for (int i = tid; i < TILE_N * 4; i += TPB) {
        const int r = i >> 2, q = i & 3;
        const long long n = nBase + r;
        float4 vx = make_float4(0.f, 0.f, 0.f, 0.f), vu = vx;
        if (n < N) { vx = x4[n * 4 + q]; vu = u4[q]; }
        *(float4*)(bufA + r * SA_N + q * 4)       = vx;
        *(float4*)(bufA + r * SA_N + 144 + q * 4) = vu;
    }
    stage_w(sW, w1, 160 * 128 / 4);
    __syncthreads();

    unsigned long long acc[RPW_N][2];
    gemm_tile<160, RPW_N, SA_N>(bufA, sW, b1, acc);
    store_act<RPW_N, SB_N, true>(acc, bufB);
    __syncthreads();
    stage_w(sW, w2, 128 * 128 / 4);
    __syncthreads();
    gemm_tile<128, RPW_N, SB_N>(bufB, sW, b2, acc);
    store_act<RPW_N, SB_N, true>(acc, bufA);   // reuse bufA with SB_N stride
    __syncthreads();
    stage_w(sW, w3, 128 * 128 / 4);
    __syncthreads();
    gemm_tile<128, RPW_N, SB_N>(bufA, sW, b3, acc);
    store_act<RPW_N, SB_N, true>(acc, bufB);
    __syncthreads();
    stage_w(sW, w4, 128 * 128 / 4);
    __syncthreads();
    gemm_tile<128, RPW_N, SB_N>(bufB, sW, b4, acc);

    const int lane = tid & 31, warp = tid >> 5, c0 = lane << 2;
    float cs0 = 0.f, cs1 = 0.f, cs2 = 0.f, cs3 = 0.f;
#pragma unroll
    for (int r = 0; r < RPW_N; r++) {
        const int row = warp * RPW_N + r;
        const long long n = nBase + row;
        if (n < N) {
            float2 lo = upk2(acc[r][0]);
            float2 hi = upk2(acc[r][1]);
            float4 v = make_float4(lo.x, lo.y, hi.x, hi.y);
            *(float4*)(n_out + n * 128 + c0) = v;
            cs0 += v.x; cs1 += v.y; cs2 += v.z; cs3 += v.w;
        }
    }
    __syncthreads();
    *(float4*)(bufA + warp * 128 + c0) = make_float4(cs0, cs1, cs2, cs3);
    __syncthreads();
    if (tid < 128) {
        float s = 0.f;
#pragma unroll
        for (int w = 0; w < 8; w++) s += bufA[w * 128 + tid];
        atomicAdd(&g_nsum[tid], s);
    }
}

// ---------------- global kernel: single-row 4-layer MLP ----------------
__global__ void global_kernel(const float* __restrict__ u,
                              const float* __restrict__ w1, const float* __restrict__ b1,
                              const float* __restrict__ w2, const float* __restrict__ b2,
                              const float* __restrict__ w3, const float* __restrict__ b3,
                              const float* __restrict__ w4, const float* __restrict__ b4,
                              float* __restrict__ g_out) {
    __shared__ float sIn[272];
    __shared__ float sH[128];
    const int t = threadIdx.x;  // 128 threads
    if (t < 16) sIn[t] = u[t];
    sIn[16 + t]  = g_nsum[t];
    sIn[144 + t] = g_esum[t];
    __syncthreads();

    float a = b1[t];
#pragma unroll 4
    for (int k = 0; k < 272; k++) a = fmaf(sIn[k], w1[k * 128 + t], a);
    a = fmaxf(a, 0.f);
    __syncthreads(); sH[t] = a; __syncthreads();

    a = b2[t];
#pragma unroll 4
    for (int k = 0; k < 128; k++) a = fmaf(sH[k], w2[k * 128 + t], a);
    a = fmaxf(a, 0.f);
    __syncthreads(); sH[t] = a; __syncthreads();

    a = b3[t];
#pragma unroll 4
    for (int k = 0; k < 128; k++) a = fmaf(sH[k], w3[k * 128 + t], a);
    a = fmaxf(a, 0.f);
    __syncthreads(); sH[t] = a; __syncthreads();

    a = b4[t];
#pragma unroll 4
    for (int k = 0; k < 128; k++) a = fmaf(sH[k], w4[k * 128 + t], a);
    g_out[t] = a;
}

// ---------------- host launcher ----------------
extern "C" void kernel_launch(void* const* d_in, const int* in_sizes, int n_in,
                              void* d_out, int out_size) {
    const float* x  = (const float*)d_in[0];
    const float* ea = (const float*)d_in[1];
    const float* u  = (const float*)d_in[2];
    const void*  ei = d_in[3];
    const float* const* W = (const float* const*)(d_in + 4);  // 24 weight/bias ptrs

    const int N = in_sizes[0] / 16;
    const int E = in_sizes[1] / 16;

    float* out   = (float*)d_out;
    float* e_out = out;
    float* n_out = out + (long long)E * 128;
    float* g_out = out + (long long)E * 128 + (long long)N * 128;

    const int SMEM_EDGE = (2 * TILE_E * SA_E + 128 * 128) * (int)sizeof(float)
                          + 2 * TILE_E * (int)sizeof(int);
    const int SMEM_NODE = (TILE_N * SA_N + TILE_N * SB_N + 160 * 128) * (int)sizeof(float);

    cudaFuncSetAttribute(edge_kernel, cudaFuncAttributeMaxDynamicSharedMemorySize, SMEM_EDGE);
    cudaFuncSetAttribute(node_kernel, cudaFuncAttributeMaxDynamicSharedMemorySize, SMEM_NODE);

    detect_kernel<<<1, TPB>>>((const unsigned*)ei, E);
    zero_kernel<<<1024, 256>>>((long long)N * 128);
    edge_kernel<<<(E + TILE_E - 1) / TILE_E, TPB, SMEM_EDGE>>>(
        x, ea, u, ei,
        W[0], W[1], W[2], W[3], W[4], W[5], W[6], W[7],
        e_out, N, E);
    node_kernel<<<(N + TILE_N - 1) / TILE_N, TPB, SMEM_NODE>>>(
        x, u,
        W[8], W[9], W[10], W[11], W[12], W[13], W[14], W[15],
        n_out, N);
    global_kernel<<<1, 128>>>(
        u,
        W[16], W[17], W[18], W[19], W[20], W[21], W[22], W[23],
        g_out);
}

// round 2
// speedup vs baseline: 1.0001x; 1.0001x over previous
#include <cuda_runtime.h>
#include <cstdint>

// ---------------------------------------------------------------------------
// MLPGraphNetwork: edge MLP -> segment_sum -> node MLP -> global MLP
// Fully fused fp32 implementation using packed fma.rn.f32x2 (FFMA2).
// ---------------------------------------------------------------------------

#define TPB 256

#define TILE_E 128
#define RPW_E  16     // rows per warp (edge kernel)
#define SA_E   132    // smem activation stride (edge)

#define TILE_N 64
#define RPW_N  8
#define SA_N   164    // node layer-1 input stride (160 wide)
#define SB_N   132    // node hidden stride

#define MAX_NODES 50000

// Scratch (static device globals are the allowed scratch mechanism)
__device__ float g_agg[MAX_NODES * 128];
__device__ float g_esum[128];
__device__ float g_nsum[128];
__device__ int   g_is64;

// ---------------- packed f32x2 helpers ----------------
__device__ __forceinline__ unsigned long long pk2(float a, float b) {
    unsigned long long r;
    asm("mov.b64 %0, {%1,%2};" : "=l"(r) : "f"(a), "f"(b));
    return r;
}
__device__ __forceinline__ float2 upk2(unsigned long long v) {
    float2 r;
    asm("mov.b64 {%0,%1}, %2;" : "=f"(r.x), "=f"(r.y) : "l"(v));
    return r;
}
__device__ __forceinline__ void fma2(unsigned long long& d,
                                     unsigned long long a,
                                     unsigned long long b) {
    asm("fma.rn.f32x2 %0, %1, %2, %0;" : "+l"(d) : "l"(a), "l"(b));
}

// ---------------- shared-memory GEMM tile ----------------
// Block = 256 threads = 8 warps. Each warp computes RPW rows x 128 cols.
// Lane owns 4 consecutive output columns (c0 = lane*4), accumulated as two
// f32x2 pairs per row. Weights in smem row-major [KIN][128]. Bias preloaded.
template <int KIN, int RPW, int STRIDE>
__device__ __forceinline__ void gemm_tile(const float* __restrict__ sIn,
                                          const float* __restrict__ sW,
                                          const float* __restrict__ gB,
                                          unsigned long long acc[RPW][2]) {
    const int lane = threadIdx.x & 31;
    const int warp = threadIdx.x >> 5;
    const int c0 = lane << 2;
    const float4 b = *(const float4*)(gB + c0);
    const unsigned long long b0 = pk2(b.x, b.y), b1 = pk2(b.z, b.w);
#pragma unroll
    for (int r = 0; r < RPW; r++) { acc[r][0] = b0; acc[r][1] = b1; }

    const float* inBase = sIn + warp * RPW * STRIDE;
#pragma unroll 1
    for (int kk = 0; kk < KIN; kk += 4) {
        const float4 w0 = *(const float4*)(sW + (kk + 0) * 128 + c0);
        const float4 w1 = *(const float4*)(sW + (kk + 1) * 128 + c0);
        const float4 w2 = *(const float4*)(sW + (kk + 2) * 128 + c0);
        const float4 w3 = *(const float4*)(sW + (kk + 3) * 128 + c0);
        unsigned long long wd[4][2];
        wd[0][0] = pk2(w0.x, w0.y); wd[0][1] = pk2(w0.z, w0.w);
        wd[1][0] = pk2(w1.x, w1.y); wd[1][1] = pk2(w1.z, w1.w);
        wd[2][0] = pk2(w2.x, w2.y); wd[2][1] = pk2(w2.z, w2.w);
        wd[3][0] = pk2(w3.x, w3.y); wd[3][1] = pk2(w3.z, w3.w);
#pragma unroll
        for (int r = 0; r < RPW; r++) {
            const float4 a = *(const float4*)(inBase + r * STRIDE + kk);
            unsigned long long t;
            t = pk2(a.x, a.x); fma2(acc[r][0], t, wd[0][0]); fma2(acc[r][1], t, wd[0][1]);
            t = pk2(a.y, a.y); fma2(acc[r][0], t, wd[1][0]); fma2(acc[r][1], t, wd[1][1]);
            t = pk2(a.z, a.z); fma2(acc[r][0], t, wd[2][0]); fma2(acc[r][1], t, wd[2][1]);
            t = pk2(a.w, a.w); fma2(acc[r][0], t, wd[3][0]); fma2(acc[r][1], t, wd[3][1]);
        }
    }
}

template <int RPW, int STRIDE, bool RELU>
__device__ __forceinline__ void store_act(unsigned long long acc[RPW][2],
                                          float* __restrict__ sOut) {
    const int lane = threadIdx.x & 31;
    const int warp = threadIdx.x >> 5;
    const int c0 = lane << 2;
#pragma unroll
    for (int r = 0; r < RPW; r++) {
        float2 lo = upk2(acc[r][0]);
        float2 hi = upk2(acc[r][1]);
        float4 v = make_float4(lo.x, lo.y, hi.x, hi.y);
        if (RELU) {
            v.x = fmaxf(v.x, 0.f); v.y = fmaxf(v.y, 0.f);
            v.z = fmaxf(v.z, 0.f); v.w = fmaxf(v.w, 0.f);
        }
        *(float4*)(sOut + (warp * RPW + r) * STRIDE + c0) = v;
    }
}

__device__ __forceinline__ void stage_w(float* __restrict__ sW,
                                        const float* __restrict__ gW, int n4) {
    const float4* s = (const float4*)gW;
    float4* d = (float4*)sW;
    for (int i = threadIdx.x; i < n4; i += TPB) d[i] = s[i];
}

// ---------------- dtype detection for edge_index ----------------
// If indices are int64 (little-endian, values < 2^31), every odd 32-bit word
// is zero. With int32 data those words are random node ids, virtually never
// all zero across 2048 samples.
__global__ void detect_kernel(const unsigned* __restrict__ p, int E) {
    if (threadIdx.x == 0) g_is64 = 1;
    __syncthreads();
    const int n = E < 2048 ? E : 2048;
    bool nz = false;
    for (int i = threadIdx.x; i < n; i += TPB)
        if (p[2 * i + 1] != 0) nz = true;
    if (nz) g_is64 = 0;
}

__global__ void zero_kernel(long long total) {
    long long i = (long long)blockIdx.x * blockDim.x + threadIdx.x;
    const long long stride = (long long)gridDim.x * blockDim.x;
    for (; i < total; i += stride) g_agg[i] = 0.f;
    if (blockIdx.x == 0 && threadIdx.x < 128) {
        g_esum[threadIdx.x] = 0.f;
        g_nsum[threadIdx.x] = 0.f;
    }
}

// ---------------- edge kernel: fused 4-layer MLP + segment_sum ----------------
__global__ void __launch_bounds__(TPB)
edge_kernel(const float* __restrict__ x, const float* __restrict__ ea,
            const float* __restrict__ u, const void* __restrict__ ei,
            const float* __restrict__ w1, const float* __restrict__ b1,
            const float* __restrict__ w2, const float* __restrict__ b2,
            const float* __restrict__ w3, const float* __restrict__ b3,
            const float* __restrict__ w4, const float* __restrict__ b4,
            float* __restrict__ e_out, int N, int E) {
    extern __shared__ float sm[];
    float* bufA = sm;                          // TILE_E * SA_E
    float* bufB = bufA + TILE_E * SA_E;        // TILE_E * SA_E
    float* sW   = bufB + TILE_E * SA_E;        // 128 * 128
    int* sSrc = (int*)(sW + 128 * 128);
    int* sDst = sSrc + TILE_E;

    const int tid = threadIdx.x;
    const long long eBase = (long long)blockIdx.x * TILE_E;
    const int is64 = g_is64;

    for (int i = tid; i < TILE_E; i += TPB) {
        long long e = eBase + i;
        int s = 0, d = 0;
        if (e < E) {
            if (is64) {
                const long long* q = (const long long*)ei;
                s = (int)q[e]; d = (int)q[E + e];
            } else {
                const int* q = (const int*)ei;
                s = q[e]; d = q[E + e];
            }
        }
        sSrc[i] = s; sDst[i] = d;
    }
    __syncthreads();

    // Stage concat([edge_attr, x[src], x[dst], u]) into bufA (64 wide)
    const float4* x4 = (const float4*)x;
    const float4* ea4 = (const float4*)ea;
    const float4* u4 = (const float4*)u;
    for (int i = tid; i < TILE_E * 4; i += TPB) {
        const int r = i >> 2, q = i & 3;
        const long long e = eBase + r;
        float4 z = make_float4(0.f, 0.f, 0.f, 0.f);
        float4 va = z, vs = z, vd = z, vu = z;
        if (e < E) {
            va = ea4[e * 4 + q];
            vs = x4[(long long)sSrc[r] * 4 + q];
            vd = x4[(long long)sDst[r] * 4 + q];
            vu = u4[q];
        }
        float* row = bufA + r * SA_E;
        *(float4*)(row + q * 4)      = va;
        *(float4*)(row + 16 + q * 4) = vs;
        *(float4*)(row + 32 + q * 4) = vd;
        *(float4*)(row + 48 + q * 4) = vu;
    }
    stage_w(sW, w1, 64 * 128 / 4);
    __syncthreads();

    unsigned long long acc[RPW_E][2];
    gemm_tile<64, RPW_E, SA_E>(bufA, sW, b1, acc);
    store_act<RPW_E, SA_E, true>(acc, bufB);
    __syncthreads();
    stage_w(sW, w2, 128 * 128 / 4);
    __syncthreads();
    gemm_tile<128, RPW_E, SA_E>(bufB, sW, b2, acc);
    store_act<RPW_E, SA_E, true>(acc, bufA);
    __syncthreads();
    stage_w(sW, w3, 128 * 128 / 4);
    __syncthreads();
    gemm_tile<128, RPW_E, SA_E>(bufA, sW, b3, acc);
    store_act<RPW_E, SA_E, true>(acc, bufB);
    __syncthreads();
    stage_w(sW, w4, 128 * 128 / 4);
    __syncthreads();
    gemm_tile<128, RPW_E, SA_E>(bufB, sW, b4, acc);

    // Epilogue: write e_out, atomic segment-sum into g_agg, column sums
    const int lane = tid & 31, warp = tid >> 5, c0 = lane << 2;
    float cs0 = 0.f, cs1 = 0.f, cs2 = 0.f, cs3 = 0.f;
#pragma unroll
    for (int r = 0; r < RPW_E; r++) {
        const int row = warp * RPW_E + r;
        const long long e = eBase + row;
        if (e < E) {
            float2 lo = upk2(acc[r][0]);
            float2 hi = upk2(acc[r][1]);
            float4 v = make_float4(lo.x, lo.y, hi.x, hi.y);
            *(float4*)(e_out + e * 128 + c0) = v;
            float* ap = g_agg + (long long)sDst[row] * 128 + c0;
            atomicAdd(ap + 0, v.x); atomicAdd(ap + 1, v.y);
            atomicAdd(ap + 2, v.z); atomicAdd(ap + 3, v.w);
            cs0 += v.x; cs1 += v.y; cs2 += v.z; cs3 += v.w;
        }
    }
    __syncthreads();
    *(float4*)(bufA + warp * 128 + c0) = make_float4(cs0, cs1, cs2, cs3);
    __syncthreads();
    if (tid < 128) {
        float s = 0.f;
#pragma unroll
        for (int w = 0; w < 8; w++) s += bufA[w * 128 + tid];
        atomicAdd(&g_esum[tid], s);
    }
}

// ---------------- node kernel: fused 4-layer MLP ----------------
__global__ void __launch_bounds__(TPB)
node_kernel(const float* __restrict__ x, const float* __restrict__ u,
            const float* __restrict__ w1, const float* __restrict__ b1,
            const float* __restrict__ w2, const float* __restrict__ b2,
            const float* __restrict__ w3, const float* __restrict__ b3,
            const float* __restrict__ w4, const float* __restrict__ b4,
            float* __restrict__ n_out, int N) {
    extern __shared__ float sm[];
    float* bufA = sm;                       // TILE_N * SA_N
    float* bufB = bufA + TILE_N * SA_N;     // TILE_N * SB_N
    float* sW   = bufB + TILE_N * SB_N;     // 160 * 128

    const int tid = threadIdx.x;
    const long long nBase = (long long)blockIdx.x * TILE_N;
    const float4* x4 = (const float4*)x;
    const float4* u4 = (const float4*)u;
    const float4* agg4 = (const float4*)g_agg;

    // Stage concat([x, agg, u]) (160 wide)
    for (int i = tid; i < TILE_N * 32; i += TPB) {
        const int r = i >> 5, q = i & 31;
        const long long n = nBase + r;
        float4 v = (n < N) ? agg4[n * 32 + q] : make_float4(0.f, 0.f, 0.f, 0.f);
        *(float4*)(bufA + r * SA_N + 16 + q * 4) = v;
    }
    for (int i = tid; i < TILE_N * 4; i += TPB) {
        const int r = i >> 2, q = i & 3;
        const long long n = nBase + r;
        float4 vx = make_float4(0.f, 0.f, 0.f, 0.f), vu = vx;
        if (n < N) { vx = x4[n * 4 + q]; vu = u4[q]; }
        *(float4*)(bufA + r * SA_N + q * 4)       = vx;
        *(float4*)(bufA + r * SA_N + 144 + q * 4) = vu;
    }
    stage_w(sW, w1, 160 * 128 / 4);
    __syncthreads();

    unsigned long long acc[RPW_N][2];
    gemm_tile<160, RPW_N, SA_N>(bufA, sW, b1, acc);
    store_act<RPW_N, SB_N, true>(acc, bufB);
    __syncthreads();
    stage_w(sW, w2, 128 * 128 / 4);
    __syncthreads();
    gemm_tile<128, RPW_N, SB_N>(bufB, sW, b2, acc);
    store_act<RPW_N, SB_N, true>(acc, bufA);   // reuse bufA with SB_N stride
    __syncthreads();
    stage_w(sW, w3, 128 * 128 / 4);
    __syncthreads();
    gemm_tile<128, RPW_N, SB_N>(bufA, sW, b3, acc);
    store_act<RPW_N, SB_N, true>(acc, bufB);
    __syncthreads();
    stage_w(sW, w4, 128 * 128 / 4);
    __syncthreads();
    gemm_tile<128, RPW_N, SB_N>(bufB, sW, b4, acc);

    const int lane = tid & 31, warp = tid >> 5, c0 = lane << 2;
    float cs0 = 0.f, cs1 = 0.f, cs2 = 0.f, cs3 = 0.f;
#pragma unroll
    for (int r = 0; r < RPW_N; r++) {
        const int row = warp * RPW_N + r;
        const long long n = nBase + row;
        if (n < N) {
            float2 lo = upk2(acc[r][0]);
            float2 hi = upk2(acc[r][1]);
            float4 v = make_float4(lo.x, lo.y, hi.x, hi.y);
            *(float4*)(n_out + n * 128 + c0) = v;
            cs0 += v.x; cs1 += v.y; cs2 += v.z; cs3 += v.w;
        }
    }
    __syncthreads();
    *(float4*)(bufA + warp * 128 + c0) = make_float4(cs0, cs1, cs2, cs3);
    __syncthreads();
    if (tid < 128) {
        float s = 0.f;
#pragma unroll
        for (int w = 0; w < 8; w++) s += bufA[w * 128 + tid];
        atomicAdd(&g_nsum[tid], s);
    }
}

// ---------------- global kernel: single-row 4-layer MLP ----------------
__global__ void global_kernel(const float* __restrict__ u,
                              const float* __restrict__ w1, const float* __restrict__ b1,
                              const float* __restrict__ w2, const float* __restrict__ b2,
                              const float* __restrict__ w3, const float* __restrict__ b3,
                              const float* __restrict__ w4, const float* __restrict__ b4,
                              float* __restrict__ g_out) {
    __shared__ float sIn[272];
    __shared__ float sH[128];
    const int t = threadIdx.x;  // 128 threads
    if (t < 16) sIn[t] = u[t];
    sIn[16 + t]  = g_nsum[t];
    sIn[144 + t] = g_esum[t];
    __syncthreads();

    float a = b1[t];
#pragma unroll 4
    for (int k = 0; k < 272; k++) a = fmaf(sIn[k], w1[k * 128 + t], a);
    a = fmaxf(a, 0.f);
    __syncthreads(); sH[t] = a; __syncthreads();

    a = b2[t];
#pragma unroll 4
    for (int k = 0; k < 128; k++) a = fmaf(sH[k], w2[k * 128 + t], a);
    a = fmaxf(a, 0.f);
    __syncthreads(); sH[t] = a; __syncthreads();

    a = b3[t];
#pragma unroll 4
    for (int k = 0; k < 128; k++) a = fmaf(sH[k], w3[k * 128 + t], a);
    a = fmaxf(a, 0.f);
    __syncthreads(); sH[t] = a; __syncthreads();

    a = b4[t];
#pragma unroll 4
    for (int k = 0; k < 128; k++) a = fmaf(sH[k], w4[k * 128 + t], a);
    g_out[t] = a;
}

// ---------------- host launcher ----------------
extern "C" void kernel_launch(void* const* d_in, const int* in_sizes, int n_in,
                              void* d_out, int out_size) {
    const float* x  = (const float*)d_in[0];
    const float* ea = (const float*)d_in[1];
    const float* u  = (const float*)d_in[2];
    const void*  ei = d_in[3];
    const float* const* W = (const float* const*)(d_in + 4);  // 24 weight/bias ptrs

    const int N = in_sizes[0] / 16;
    const int E = in_sizes[1] / 16;

    float* out   = (float*)d_out;
    float* e_out = out;
    float* n_out = out + (long long)E * 128;
    float* g_out = out + (long long)E * 128 + (long long)N * 128;

    const int SMEM_EDGE = (2 * TILE_E * SA_E + 128 * 128) * (int)sizeof(float)
                          + 2 * TILE_E * (int)sizeof(int);
    const int SMEM_NODE = (TILE_N * SA_N + TILE_N * SB_N + 160 * 128) * (int)sizeof(float);

    cudaFuncSetAttribute(edge_kernel, cudaFuncAttributeMaxDynamicSharedMemorySize, SMEM_EDGE);
    cudaFuncSetAttribute(node_kernel, cudaFuncAttributeMaxDynamicSharedMemorySize, SMEM_NODE);

    detect_kernel<<<1, TPB>>>((const unsigned*)ei, E);
    zero_kernel<<<1024, 256>>>((long long)N * 128);
    edge_kernel<<<(E + TILE_E - 1) / TILE_E, TPB, SMEM_EDGE>>>(
        x, ea, u, ei,
        W[0], W[1], W[2], W[3], W[4], W[5], W[6], W[7],
        e_out, N, E);
    node_kernel<<<(N + TILE_N - 1) / TILE_N, TPB, SMEM_NODE>>>(
        x, u,
        W[8], W[9], W[10], W[11], W[12], W[13], W[14], W[15],
        n_out, N);
    global_kernel<<<1, 128>>>(
        u,
        W[16], W[17], W[18], W[19], W[20], W[21], W[22], W[23],
        g_out);
}

// round 4
// speedup vs baseline: 1.7639x; 1.7637x over previous
#include <cuda_runtime.h>
#include <cuda_bf16.h>
#include <cstdint>

#define TPB 512
#define MAX_NODES 50000

// ---------------- device scratch ----------------
__device__ float g_agg[MAX_NODES * 128];
__device__ float g_esum[128];
__device__ float g_nsum[128];
__device__ int   g_is64;
// prepped weights: transposed [n][k], bf16 hi/lo, blocked SW128 (128-row tiles). 8 slots.
__device__ __align__(16) unsigned char g_Bh[8 * 49152];
__device__ __align__(16) unsigned char g_Bl[8 * 49152];

// ---------------- helpers ----------------
__device__ __forceinline__ uint32_t s2u(const void* p) {
    uint32_t a;
    asm("{ .reg .u64 t; cvta.to.shared.u64 t, %1; cvt.u32.u64 %0, t; }" : "=r"(a) : "l"(p));
    return a;
}

// blocked SW128 byte offset for bf16 element (row, k) in a tile with ROWS rows.
// atom = 8 rows x 64 bf16 (1024B); atom-col stride = ROWS*128 bytes.
template <int ROWS>
__device__ __forceinline__ uint32_t aoff(int row, int k) {
    uint32_t b = ((uint32_t)(row >> 3) << 10) + (uint32_t)(k >> 6) * (uint32_t)(ROWS * 128)
               + ((uint32_t)(row & 7) << 7) + ((uint32_t)(k & 63) << 1);
    return b ^ ((b >> 3) & 0x70);
}

__device__ __forceinline__ void split2(float v0, float v1, uint32_t& hw, uint32_t& lw) {
    __nv_bfloat16 h0 = __float2bfloat16(v0), h1 = __float2bfloat16(v1);
    __nv_bfloat16 l0 = __float2bfloat16(v0 - __bfloat162float(h0));
    __nv_bfloat16 l1 = __float2bfloat16(v1 - __bfloat162float(h1));
    hw = (uint32_t)__bfloat16_as_ushort(h0) | ((uint32_t)__bfloat16_as_ushort(h1) << 16);
    lw = (uint32_t)__bfloat16_as_ushort(l0) | ((uint32_t)__bfloat16_as_ushort(l1) << 16);
}
__device__ __forceinline__ void store_pair2(char* Ah, char* Al, uint32_t off,
                                            float v0, float v1) {
    uint32_t hw, lw;
    split2(v0, v1, hw, lw);
    *(uint32_t*)(Ah + off) = hw;
    *(uint32_t*)(Al + off) = lw;
}
__device__ __forceinline__ void copy16(char* dst, const unsigned char* src, int bytes) {
    float4* d = (float4*)dst;
    const float4* s = (const float4*)src;
    for (int i = threadIdx.x; i < bytes / 16; i += (int)blockDim.x) d[i] = s[i];
}

// ---------------- mma.sync + ldmatrix ----------------
__device__ __forceinline__ void ldsm_x4(uint32_t* r, uint32_t addr) {
    asm volatile("ldmatrix.sync.aligned.m8n8.x4.shared.b16 {%0,%1,%2,%3}, [%4];"
                 : "=r"(r[0]), "=r"(r[1]), "=r"(r[2]), "=r"(r[3]) : "r"(addr));
}
__device__ __forceinline__ void ldsm_x2(uint32_t* r, uint32_t addr) {
    asm volatile("ldmatrix.sync.aligned.m8n8.x2.shared.b16 {%0,%1}, [%2];"
                 : "=r"(r[0]), "=r"(r[1]) : "r"(addr));
}
__device__ __forceinline__ void mma_bf16(float* c, const uint32_t* a, const uint32_t* b) {
    asm volatile(
        "mma.sync.aligned.m16n8k16.row.col.f32.bf16.bf16.f32 "
        "{%0,%1,%2,%3}, {%4,%5,%6,%7}, {%8,%9}, {%0,%1,%2,%3};"
        : "+f"(c[0]), "+f"(c[1]), "+f"(c[2]), "+f"(c[3])
        : "r"(a[0]), "r"(a[1]), "r"(a[2]), "r"(a[3]), "r"(b[0]), "r"(b[1]));
}

// One emulated-fp32 layer: acc = Ah*Bh + Ah*Bl + Al*Bh over K (multiple of 16).
// Warp computes MT*16 rows x 64 cols (8 n-tiles).
template <int AROWS, int MT>
__device__ __forceinline__ void layer_mma(uint32_t ahb, uint32_t alb,
                                          uint32_t whb, uint32_t wlb,
                                          int K, int mrow0, int ncol0,
                                          float acc[MT * 8][4]) {
    const int lane = threadIdx.x & 31;
    const int aRow = (lane & 7) + ((lane >> 3) & 1) * 8;
    const int aKc  = (lane >> 4) * 8;
    const int bRow = lane & 7;
    const int bKc  = ((lane >> 3) & 1) * 8;
#pragma unroll
    for (int i = 0; i < MT * 8; i++) {
        acc[i][0] = 0.f; acc[i][1] = 0.f; acc[i][2] = 0.f; acc[i][3] = 0.f;
    }
#pragma unroll 1
    for (int k0 = 0; k0 < K; k0 += 16) {
        uint32_t ah[MT][4], al[MT][4];
#pragma unroll
        for (int mt = 0; mt < MT; mt++) {
            uint32_t off = aoff<AROWS>(mrow0 + mt * 16 + aRow, k0 + aKc);
            ldsm_x4(ah[mt], ahb + off);
            ldsm_x4(al[mt], alb + off);
        }
#pragma unroll
        for (int nt = 0; nt < 8; nt++) {
            uint32_t off = aoff<128>(ncol0 + nt * 8 + bRow, k0 + bKc);
            uint32_t bh[2], bl[2];
            ldsm_x2(bh, whb + off);
            ldsm_x2(bl, wlb + off);
#pragma unroll
            for (int mt = 0; mt < MT; mt++) {
                mma_bf16(acc[mt * 8 + nt], ah[mt], bh);
                mma_bf16(acc[mt * 8 + nt], ah[mt], bl);
                mma_bf16(acc[mt * 8 + nt], al[mt], bh);
            }
        }
    }
}

// Epilogue: add bias (+relu, split hi/lo back into A smem) or write fp32 outS (stride 128).
template <int AROWS, int MT, bool LAST>
__device__ __forceinline__ void layer_epi(float acc[MT * 8][4], const float* sBias,
                                          char* Ah, char* Al, float* outS,
                                          int mrow0, int ncol0) {
    const int lane = threadIdx.x & 31;
    const int r0 = lane >> 2, cOff = (lane & 3) * 2;
#pragma unroll
    for (int mt = 0; mt < MT; mt++) {
#pragma unroll
        for (int nt = 0; nt < 8; nt++) {
            const int col = ncol0 + nt * 8 + cOff;
            const float b0 = sBias[col], b1 = sBias[col + 1];
            float* a = acc[mt * 8 + nt];
            const int row = mrow0 + mt * 16 + r0;
            if (LAST) {
                outS[row * 128 + col]           = a[0] + b0;
                outS[row * 128 + col + 1]       = a[1] + b1;
                outS[(row + 8) * 128 + col]     = a[2] + b0;
                outS[(row + 8) * 128 + col + 1] = a[3] + b1;
            } else {
                store_pair2(Ah, Al, aoff<AROWS>(row, col),
                            fmaxf(a[0] + b0, 0.f), fmaxf(a[1] + b1, 0.f));
                store_pair2(Ah, Al, aoff<AROWS>(row + 8, col),
                            fmaxf(a[2] + b0, 0.f), fmaxf(a[3] + b1, 0.f));
            }
        }
    }
}

// ---------------- prep kernels ----------------
__global__ void detect_kernel(const unsigned* __restrict__ p, int E) {
    if (threadIdx.x == 0) g_is64 = 1;
    __syncthreads();
    const int n = E < 2048 ? E : 2048;
    bool nz = false;
    for (int i = threadIdx.x; i < n; i += 256)
        if (p[2 * i + 1] != 0) nz = true;
    if (nz) g_is64 = 0;
}
__global__ void zero_kernel(long long total) {
    long long i = (long long)blockIdx.x * blockDim.x + threadIdx.x;
    const long long stride = (long long)gridDim.x * blockDim.x;
    for (; i < total; i += stride) g_agg[i] = 0.f;
    if (blockIdx.x == 0 && threadIdx.x < 128) {
        g_esum[threadIdx.x] = 0.f;
        g_nsum[threadIdx.x] = 0.f;
    }
}
// transpose w[K][128] -> B[n][k] bf16 hi/lo, blocked SW128 (128-row tiles)
__global__ void prep_kernel(const float* w0, const float* w1, const float* w2, const float* w3,
                            const float* w4, const float* w5, const float* w6, const float* w7) {
    const float* ws[8] = {w0, w1, w2, w3, w4, w5, w6, w7};
    const int KR[8] = {64, 128, 128, 128, 160, 128, 128, 128};
    const int KP[8] = {64, 128, 128, 128, 192, 128, 128, 128};
    const int s = blockIdx.x;
    const float* w = ws[s];
    const int kr = KR[s], kp = KP[s];
    unsigned char* bh = g_Bh + s * 49152;
    unsigned char* bl = g_Bl + s * 49152;
    for (int i = threadIdx.x; i < 128 * kp; i += 256) {
        int n = i & 127, k = i >> 7;
        float v = (k < kr) ? w[k * 128 + n] : 0.f;
        __nv_bfloat16 h = __float2bfloat16(v);
        __nv_bfloat16 l = __float2bfloat16(v - __bfloat162float(h));
        uint32_t o = aoff<128>(n, k);
        *(__nv_bfloat16*)(bh + o) = h;
        *(__nv_bfloat16*)(bl + o) = l;
    }
}

// ---------------- edge kernel: 256-row tiles, 512 threads ----------------
// smem: Ah 0..64K | Al 64K..128K | Wh 128K..160K | Wl 160K..192K
//       sBias @196608(512B) | sSrc @197120(1KB) | sDst @198144(1KB)
// outS (256x128 fp32 = 128KB) overlaps Ah+Al.
#define E_SMEM (199168 + 1024)

__global__ void __launch_bounds__(TPB, 1)
edge_kernel(const float* __restrict__ x, const float* __restrict__ ea,
            const float* __restrict__ u, const void* __restrict__ ei,
            const float* __restrict__ b1, const float* __restrict__ b2,
            const float* __restrict__ b3, const float* __restrict__ b4,
            float* __restrict__ e_out, int N, int E) {
    extern __shared__ __align__(16) char smraw[];
    char* sm = (char*)((((uintptr_t)smraw) + 1023) & ~(uintptr_t)1023);
    char* Ah = sm;
    char* Al = sm + 65536;
    char* Wh = sm + 131072;
    char* Wl = sm + 163840;
    float* outS  = (float*)sm;
    float* sBias = (float*)(sm + 196608);
    int* sSrc = (int*)(sm + 197120);
    int* sDst = (int*)(sm + 198144);
    const uint32_t ahb = s2u(Ah), alb = s2u(Al), whb = s2u(Wh), wlb = s2u(Wl);

    const int tid = threadIdx.x, wid = tid >> 5;
    const int mrow0 = (wid >> 1) * 32, ncol0 = (wid & 1) * 64;
    const long long eBase = (long long)blockIdx.x * 256;
    const int is64 = g_is64;

    for (int i = tid; i < 256; i += TPB) {
        long long e = eBase + i;
        int s = 0, d = 0;
        if (e < E) {
            if (is64) { const long long* q = (const long long*)ei; s = (int)q[e]; d = (int)q[E + e]; }
            else      { const int* q = (const int*)ei;             s = q[e];      d = q[E + e]; }
        }
        sSrc[i] = s; sDst[i] = d;
    }
    __syncthreads();

    // stage layer-1 A: concat(ea, x[src], x[dst], u), K=64, 256 rows
    for (int i = tid; i < 256 * 32; i += TPB) {
        int row = i & 255, k = (i >> 8) * 2;
        long long e = eBase + row;
        float v0 = 0.f, v1 = 0.f;
        if (e < E) {
            if (k < 16)      { v0 = ea[e * 16 + k];            v1 = ea[e * 16 + k + 1]; }
            else if (k < 32) { long long s = sSrc[row]; v0 = x[s * 16 + k - 16]; v1 = x[s * 16 + k - 15]; }
            else if (k < 48) { long long d = sDst[row]; v0 = x[d * 16 + k - 32]; v1 = x[d * 16 + k - 31]; }
            else             { v0 = u[k - 48];                 v1 = u[k - 47]; }
        }
        store_pair2(Ah, Al, aoff<256>(row, k), v0, v1);
    }

    const float* bs[4] = {b1, b2, b3, b4};
    const int Ks[4]  = {64, 128, 128, 128};
    const int wsz[4] = {16384, 32768, 32768, 32768};

    float acc[16][4];
#pragma unroll 1
    for (int l = 0; l < 4; l++) {
        copy16(Wh, g_Bh + l * 49152, wsz[l]);
        copy16(Wl, g_Bl + l * 49152, wsz[l]);
        if (tid < 128) sBias[tid] = bs[l][tid];
        __syncthreads();
        layer_mma<256, 2>(ahb, alb, whb, wlb, Ks[l], mrow0, ncol0, acc);
        __syncthreads();
        if (l < 3) layer_epi<256, 2, false>(acc, sBias, Ah, Al, nullptr, mrow0, ncol0);
        else       layer_epi<256, 2, true>(acc, sBias, nullptr, nullptr, outS, mrow0, ncol0);
    }
    __syncthreads();

    // final: coalesced e_out stores + segment-sum atomics
    for (int i = tid; i < 256 * 32; i += TPB) {
        int row = i >> 5, q = i & 31;
        long long e = eBase + row;
        if (e < E) {
            float4 v = *(float4*)(outS + row * 128 + q * 4);
            *(float4*)(e_out + e * 128 + q * 4) = v;
            float* ap = g_agg + (long long)sDst[row] * 128 + q * 4;
            atomicAdd(ap + 0, v.x); atomicAdd(ap + 1, v.y);
            atomicAdd(ap + 2, v.z); atomicAdd(ap + 3, v.w);
        }
    }
}

// ---------------- node kernel: 128-row tiles, 512 threads ----------------
// smem: Ah 0..48K | Al 48K..96K | Wh 96K..144K | Wl 144K..192K | sBias @196608
// outS (128x128 fp32 = 64KB) overlaps Ah.
#define N_SMEM (197120 + 1024)

__global__ void __launch_bounds__(TPB, 1)
node_kernel(const float* __restrict__ x, const float* __restrict__ u,
            const float* __restrict__ b1, const float* __restrict__ b2,
            const float* __restrict__ b3, const float* __restrict__ b4,
            float* __restrict__ n_out, int N) {
    extern __shared__ __align__(16) char smraw[];
    char* sm = (char*)((((uintptr_t)smraw) + 1023) & ~(uintptr_t)1023);
    char* Ah = sm;
    char* Al = sm + 49152;
    char* Wh = sm + 98304;
    char* Wl = sm + 147456;
    float* outS  = (float*)sm;
    float* sBias = (float*)(sm + 196608);
    const uint32_t ahb = s2u(Ah), alb = s2u(Al), whb = s2u(Wh), wlb = s2u(Wl);

    const int tid = threadIdx.x, wid = tid >> 5;
    const int mrow0 = (wid >> 1) * 16, ncol0 = (wid & 1) * 64;
    const long long nBase = (long long)blockIdx.x * 128;
    const int lim = (int)(((N - nBase) < 128) ? (N - nBase) : 128);

    // esum contribution: column sums of g_agg rows owned by this block
    {
        int col = tid & 127, quarter = tid >> 7;
        float s = 0.f;
        for (int r = quarter * 32; r < quarter * 32 + 32 && r < lim; r++)
            s += g_agg[(nBase + r) * 128 + col];
        atomicAdd(&g_esum[col], s);
    }

    // stage layer-1 A: concat(x, agg, u) padded to K=192
    for (int i = tid; i < 128 * 96; i += TPB) {
        int row = i & 127, k = (i >> 7) * 2;
        long long n = nBase + row;
        float v0 = 0.f, v1 = 0.f;
        if (n < N) {
            if (k < 16)       { v0 = x[n * 16 + k];            v1 = x[n * 16 + k + 1]; }
            else if (k < 144) { v0 = g_agg[n * 128 + k - 16];  v1 = g_agg[n * 128 + k - 15]; }
            else if (k < 160) { v0 = u[k - 144];               v1 = u[k - 143]; }
        }
        store_pair2(Ah, Al, aoff<128>(row, k), v0, v1);
    }

    const float* bs[4] = {b1, b2, b3, b4};
    const int Ks[4]  = {192, 128, 128, 128};
    const int wsz[4] = {49152, 32768, 32768, 32768};

    float acc[8][4];
#pragma unroll 1
    for (int l = 0; l < 4; l++) {
        copy16(Wh, g_Bh + (4 + l) * 49152, wsz[l]);
        copy16(Wl, g_Bl + (4 + l) * 49152, wsz[l]);
        if (tid < 128) sBias[tid] = bs[l][tid];
        __syncthreads();
        layer_mma<128, 1>(ahb, alb, whb, wlb, Ks[l], mrow0, ncol0, acc);
        __syncthreads();
        if (l < 3) layer_epi<128, 1, false>(acc, sBias, Ah, Al, nullptr, mrow0, ncol0);
        else       layer_epi<128, 1, true>(acc, sBias, nullptr, nullptr, outS, mrow0, ncol0);
    }
    __syncthreads();

    for (int i = tid; i < 128 * 32; i += TPB) {
        int row = i >> 5, q = i & 31;
        long long n = nBase + row;
        if (n < N)
            *(float4*)(n_out + n * 128 + q * 4) = *(float4*)(outS + row * 128 + q * 4);
    }
    __syncthreads();
    {
        int col = tid & 127, quarter = tid >> 7;
        float s = 0.f;
        for (int r = quarter * 32; r < quarter * 32 + 32 && r < lim; r++)
            s += outS[r * 128 + col];
        atomicAdd(&g_nsum[col], s);
    }
}

// ---------------- global kernel ----------------
__global__ void global_kernel(const float* __restrict__ u,
                              const float* __restrict__ w1, const float* __restrict__ b1,
                              const float* __restrict__ w2, const float* __restrict__ b2,
                              const float* __restrict__ w3, const float* __restrict__ b3,
                              const float* __restrict__ w4, const float* __restrict__ b4,
                              float* __restrict__ g_out) {
    __shared__ float sIn[272];
    __shared__ float sH[128];
    const int t = threadIdx.x;  // 128 threads
    if (t < 16) sIn[t] = u[t];
    sIn[16 + t]  = g_nsum[t];
    sIn[144 + t] = g_esum[t];
    __syncthreads();

    float a = b1[t];
#pragma unroll 4
    for (int k = 0; k < 272; k++) a = fmaf(sIn[k], w1[k * 128 + t], a);
    a = fmaxf(a, 0.f);
    __syncthreads(); sH[t] = a; __syncthreads();

    a = b2[t];
#pragma unroll 4
    for (int k = 0; k < 128; k++) a = fmaf(sH[k], w2[k * 128 + t], a);
    a = fmaxf(a, 0.f);
    __syncthreads(); sH[t] = a; __syncthreads();

    a = b3[t];
#pragma unroll 4
    for (int k = 0; k < 128; k++) a = fmaf(sH[k], w3[k * 128 + t], a);
    a = fmaxf(a, 0.f);
    __syncthreads(); sH[t] = a; __syncthreads();

    a = b4[t];
#pragma unroll 4
    for (int k = 0; k < 128; k++) a = fmaf(sH[k], w4[k * 128 + t], a);
    g_out[t] = a;
}

// ---------------- host launcher ----------------
extern "C" void kernel_launch(void* const* d_in, const int* in_sizes, int n_in,
                              void* d_out, int out_size) {
    const float* x  = (const float*)d_in[0];
    const float* ea = (const float*)d_in[1];
    const float* u  = (const float*)d_in[2];
    const void*  ei = d_in[3];

    const int N = in_sizes[0] / 16;
    const int E = in_sizes[1] / 16;

    float* out   = (float*)d_out;
    float* e_out = out;
    float* n_out = out + (long long)E * 128;
    float* g_out = out + (long long)E * 128 + (long long)N * 128;

    cudaFuncSetAttribute(edge_kernel, cudaFuncAttributeMaxDynamicSharedMemorySize, E_SMEM);
    cudaFuncSetAttribute(node_kernel, cudaFuncAttributeMaxDynamicSharedMemorySize, N_SMEM);

    detect_kernel<<<1, 256>>>((const unsigned*)ei, E);
    zero_kernel<<<1024, 256>>>((long long)N * 128);
    prep_kernel<<<8, 256>>>((const float*)d_in[4],  (const float*)d_in[6],
                            (const float*)d_in[8],  (const float*)d_in[10],
                            (const float*)d_in[12], (const float*)d_in[14],
                            (const float*)d_in[16], (const float*)d_in[18]);
    edge_kernel<<<(E + 255) / 256, TPB, E_SMEM>>>(
        x, ea, u, ei,
        (const float*)d_in[5], (const float*)d_in[7],
        (const float*)d_in[9], (const float*)d_in[11],
        e_out, N, E);
    node_kernel<<<(N + 127) / 128, TPB, N_SMEM>>>(
        x, u,
        (const float*)d_in[13], (const float*)d_in[15],
        (const float*)d_in[17], (const float*)d_in[19],
        n_out, N);
    global_kernel<<<1, 128>>>(
        u,
        (const float*)d_in[20], (const float*)d_in[21],
        (const float*)d_in[22], (const float*)d_in[23],
        (const float*)d_in[24], (const float*)d_in[25],
        (const float*)d_in[26], (const float*)d_in[27],
        g_out);
}